// round 13
// baseline (speedup 1.0000x reference)
#include <cuda_runtime.h>
#include <cuda_bf16.h>

// out[b,s,d] = in[b,s,d] + pe(s,d)
//   pe(s,d) = sin(s * f(d)) if d even else cos(s * f(d)),  f(d) = 10000^(-2d/D)
//
// B=8, S=4096, D=1024, fp32. 268 MB/launch. Best: R12 = 45.57us (5.88 TB/s).
// R13 = R12 with ONE isolated change: grid 592 -> 444. With 80 regs and
// __launch_bounds__(256,3), only 3 blocks/SM = 444 are resident; grid 592
// created a second, 1/3-populated block-wave (148 blocks running on an
// otherwise idle chip = low-BW tail). Grid 444 = exactly one resident wave;
// every block starts at t=0; rows split 9 or 10 per block (92% slot balance
// at FULL chip bandwidth, vs a long 33%-bandwidth tail before).

constexpr int D    = 1024;
constexpr int S    = 4096;
constexpr int B    = 8;
constexpr int TPB  = D / 4;       // 256 threads, one float4 of d each
constexpr int GRID = 3 * 148;     // 444 = exactly the resident block capacity
constexpr int SD   = S * TPB;     // float4 stride between batches

__global__ __launch_bounds__(TPB, 3)
void pe_add_kernel(const float4* __restrict__ in, float4* __restrict__ out) {
    const int d4 = threadIdx.x;
    const int d  = d4 * 4;

    // f(d+j) = exp2( -(d+j) * 2*log2(10000)/1024 ), row-independent
    const float c = -2.0f * 13.287712379549449f / (float)D;
    const float f0 = exp2f(c * (float)(d + 0));
    const float f1 = exp2f(c * (float)(d + 1));
    const float f2 = exp2f(c * (float)(d + 2));
    const float f3 = exp2f(c * (float)(d + 3));

    int s   = blockIdx.x;
    int row = s * TPB + d4;

    // Prologue: entire row s (all 8 batches) in flight
    float4 A[B];
    #pragma unroll
    for (int b = 0; b < B; ++b) A[b] = __ldcs(&in[b * SD + row]);

    while (true) {
        const int snext = s + GRID;
        const bool more = snext < S;
        const int rown  = snext * TPB + d4;

        // Prefetch FIRST: 8 loads issued before any MUFU/store work
        float4 N[B];
        if (more) {
            #pragma unroll
            for (int b = 0; b < B; ++b) N[b] = __ldcs(&in[b * SD + rown]);
        }

        const float fs = (float)s;
        float4 pe;                      // d%4==0: x,z even (sin); y,w odd (cos)
        pe.x = __sinf(fs * f0);
        pe.y = __cosf(fs * f1);
        pe.z = __sinf(fs * f2);
        pe.w = __cosf(fs * f3);

        // Store row s (depends only on A, already landed, and pe)
        #pragma unroll
        for (int b = 0; b < B; ++b) {
            float4 o;
            o.x = A[b].x + pe.x; o.y = A[b].y + pe.y;
            o.z = A[b].z + pe.z; o.w = A[b].w + pe.w;
            __stcs(&out[b * SD + row], o);
        }

        if (!more) break;
        #pragma unroll
        for (int b = 0; b < B; ++b) A[b] = N[b];
        s = snext;
        row = rown;
    }
}

extern "C" void kernel_launch(void* const* d_in, const int* in_sizes, int n_in,
                              void* d_out, int out_size) {
    (void)in_sizes; (void)n_in; (void)out_size;
    const float4* in  = (const float4*)d_in[0];
    float4*       out = (float4*)d_out;
    pe_add_kernel<<<GRID, TPB>>>(in, out);
}

// round 14
// speedup vs baseline: 1.0122x; 1.0122x over previous
#include <cuda_runtime.h>
#include <cuda_bf16.h>

// out[b,s,d] = in[b,s,d] + pe(s,d)
//   pe(s,d) = sin(s * f(d)) if d even else cos(s * f(d)),  f(d) = 10000^(-2d/D)
//
// B=8, S=4096, D=1024, fp32. 268 MB/launch.
// R14 = EXACT replication of R12 (best: 45.568us, 5.88 TB/s sustained) to
// verify the 45.6 vs 47.6 bimodality is config, not noise (rigor.md).
// Config: grid 592 (4*148; 3 resident/SM + back-fill tail smooths better
// than clean 444 — R13 falsified the one-wave theory), LB(256,3), full-width
// 8-load next-row prefetch issued FIRST in the loop body, .cs loads+stores,
// float4/256-thread mapping, rotation copy kept (R11 showed removing it
// breaks ptxas's schedule).

constexpr int D    = 1024;
constexpr int S    = 4096;
constexpr int B    = 8;
constexpr int TPB  = D / 4;       // 256 threads, one float4 of d each
constexpr int GRID = 4 * 148;     // 592 blocks, grid-stride over s
constexpr int SD   = S * TPB;     // float4 stride between batches

__global__ __launch_bounds__(TPB, 3)
void pe_add_kernel(const float4* __restrict__ in, float4* __restrict__ out) {
    const int d4 = threadIdx.x;
    const int d  = d4 * 4;

    // f(d+j) = exp2( -(d+j) * 2*log2(10000)/1024 ), row-independent
    const float c = -2.0f * 13.287712379549449f / (float)D;
    const float f0 = exp2f(c * (float)(d + 0));
    const float f1 = exp2f(c * (float)(d + 1));
    const float f2 = exp2f(c * (float)(d + 2));
    const float f3 = exp2f(c * (float)(d + 3));

    int s   = blockIdx.x;
    int row = s * TPB + d4;

    // Prologue: entire row s (all 8 batches) in flight
    float4 A[B];
    #pragma unroll
    for (int b = 0; b < B; ++b) A[b] = __ldcs(&in[b * SD + row]);

    while (true) {
        const int snext = s + GRID;
        const bool more = snext < S;
        const int rown  = snext * TPB + d4;

        // Prefetch FIRST: 8 loads issued before any MUFU/store work, so
        // read-issue never pauses at the top of the iteration and the MUFU
        // latency below hides under the in-flight loads.
        float4 N[B];
        if (more) {
            #pragma unroll
            for (int b = 0; b < B; ++b) N[b] = __ldcs(&in[b * SD + rown]);
        }

        const float fs = (float)s;
        float4 pe;                      // d%4==0: x,z even (sin); y,w odd (cos)
        pe.x = __sinf(fs * f0);
        pe.y = __cosf(fs * f1);
        pe.z = __sinf(fs * f2);
        pe.w = __cosf(fs * f3);

        // Store row s (depends only on A, already landed, and pe)
        #pragma unroll
        for (int b = 0; b < B; ++b) {
            float4 o;
            o.x = A[b].x + pe.x; o.y = A[b].y + pe.y;
            o.z = A[b].z + pe.z; o.w = A[b].w + pe.w;
            __stcs(&out[b * SD + row], o);
        }

        if (!more) break;
        #pragma unroll
        for (int b = 0; b < B; ++b) A[b] = N[b];
        s = snext;
        row = rown;
    }
}

extern "C" void kernel_launch(void* const* d_in, const int* in_sizes, int n_in,
                              void* d_out, int out_size) {
    (void)in_sizes; (void)n_in; (void)out_size;
    const float4* in  = (const float4*)d_in[0];
    float4*       out = (float4*)d_out;
    pe_add_kernel<<<GRID, TPB>>>(in, out);
}